// round 5
// baseline (speedup 1.0000x reference)
#include <cuda_runtime.h>
#include <cuda_fp16.h>
#include <cstdint>

#define MR     32
#define NCOLS  10000
#define KDIM   10000
#define NB     157        // column blocks of 64 (157*64 = 10048 padded)
#define BN     64
#define KCH    625        // k-chunks of 16
#define NPCH   628        // padded chunk count for Y buffers
#define STAGES 5
#define KSPLIT 16
#define NTILES (NB * KSPLIT)
#define GRID   592        // 4 CTAs/SM * 148 SMs, single wave
#define STGB   9216       // bytes per pipeline stage (A 6144 + Y 3072)
#define INV2048 (1.0f/2048.0f)

// ---------------- device scratch (allocation-free) ----------------
__device__ __align__(16) __half g_Apk[(size_t)NB * KCH * 2048];     // ~402 MB
__device__ __align__(16) __half g_Yp[2][(size_t)NPCH * 1024];
__device__ __align__(16) float  g_Zp[(size_t)KSPLIT * NB * 2048];   // split-K partials
__device__ float  g_B[NB * BN * MR];
__device__ float  g_Wp[MR * MR];
__device__ int    g_cnt[NB];
__device__ int    g_tix[32];      // per-pass ticket counters

// ---------------- helpers ----------------
__device__ __forceinline__ void cpa16(uint32_t d, const void* s) {
    asm volatile("cp.async.cg.shared.global [%0], [%1], 16;" :: "r"(d), "l"(s));
}
__device__ __forceinline__ void ldm4(uint32_t* r, uint32_t a) {
    asm volatile("ldmatrix.sync.aligned.m8n8.x4.shared.b16 {%0,%1,%2,%3}, [%4];"
        : "=r"(r[0]), "=r"(r[1]), "=r"(r[2]), "=r"(r[3]) : "r"(a));
}
__device__ __forceinline__ void mma_(float* c, const uint32_t* a, uint32_t b0, uint32_t b1) {
    asm volatile("mma.sync.aligned.m16n8k16.row.col.f32.f16.f16.f32 "
        "{%0,%1,%2,%3}, {%4,%5,%6,%7}, {%8,%9}, {%0,%1,%2,%3};"
        : "+f"(c[0]), "+f"(c[1]), "+f"(c[2]), "+f"(c[3])
        : "r"(a[0]), "r"(a[1]), "r"(a[2]), "r"(a[3]), "r"(b0), "r"(b1));
}
__device__ __forceinline__ void hilo(float v, __half& h, __half& l) {
    h = __float2half_rn(v);
    l = __float2half_rn((v - __half2float(h)) * 2048.0f);
}

// ---------------- 0. reset counters (per graph replay) ----------------
__global__ void k_reset() {
    int t = threadIdx.x;
    if (t < 32) g_tix[t] = 0;
    if (t < NB) g_cnt[t] = 0;
    for (int i = t + 128; i < NB; i += 128) g_cnt[i] = 0;
}

// ---------------- 1. W projection (verified) ----------------
__global__ void k_project(const float* __restrict__ W) {
    int r = threadIdx.x;
    if (r >= MR) return;
    float a[32], u[32];
    float s = 0.0f;
    for (int i = 0; i < 32; i++) { a[i] = W[r * 32 + i]; u[i] = fabsf(a[i]); s += u[i]; }
    const float v = 0.99f;
    if (s > v) {
        for (int i = 1; i < 32; i++) {
            float key = u[i]; int j = i - 1;
            while (j >= 0 && u[j] < key) { u[j + 1] = u[j]; j--; }
            u[j + 1] = key;
        }
        float cs = 0.0f; int rho = 0;
        for (int i = 0; i < 32; i++) {
            cs += u[i];
            if (u[i] - (cs - v) / (float)(i + 1) > 0.0f) rho++;
        }
        float cs2 = 0.0f;
        for (int i = 0; i < rho; i++) cs2 += u[i];
        float theta = (cs2 - v) / (float)rho;
        for (int i = 0; i < 32; i++) {
            float m = fmaxf(fabsf(a[i]) - theta, 0.0f);
            a[i] = (a[i] > 0.0f) ? m : ((a[i] < 0.0f) ? -m : 0.0f);
        }
    }
    for (int i = 0; i < 32; i++) g_Wp[r * 32 + i] = a[i];
}

// ---------------- 2. Convert A -> blocked fp16 hi/lo (verified) ----------------
__global__ void k_convA(const float* __restrict__ A) {
    __shared__ __align__(16) float sA[16][68];
    int b  = blockIdx.x;               // nb*KCH + kc
    int nb = b / KCH, kc = b % KCH;
    int t  = threadIdx.x;
    int k0 = kc * 16, c0 = nb * BN;
    for (int e = t; e < 1024; e += 128) {
        int kk = e >> 6, c = e & 63;
        int gc = c0 + c;
        float v0 = 0.0f;
        if (gc < NCOLS) v0 = A[(size_t)(k0 + kk) * NCOLS + gc];
        sA[kk][c] = v0;
    }
    __syncthreads();
    __half* dst = &g_Apk[(size_t)b * 2048];
    for (int e = t; e < 1024; e += 128) {
        int c = e >> 4, kk = e & 15;
        __half h, l; hilo(sA[kk][c], h, l);
        dst[e] = h;
        dst[1024 + e] = l;
    }
}

// ---------------- 3. T = Omega_1 @ U -> Y[0] (verified) ----------------
__global__ void k_T(const float* __restrict__ Om1, const float* __restrict__ U) {
    __shared__ float sOm[MR * 64];
    int t = threadIdx.x;
    for (int i = t; i < MR * 64; i += 128) sOm[i] = Om1[i];
    __syncthreads();
    int kc = blockIdx.x;
    __half* dst = &g_Yp[0][(size_t)kc * 1024];
    for (int e = t; e < 512; e += 128) {
        int m = e >> 4, kk = e & 15;
        int k = kc * 16 + kk;
        float v = 0.f;
        #pragma unroll
        for (int p = 0; p < 64; p++) v += sOm[m * 64 + p] * U[(size_t)p * NCOLS + k];
        __half h, l; hilo(v, h, l);
        dst[m * 16 + kk] = h;
        dst[512 + m * 16 + kk] = l;
    }
}

// ---------------- 4. Persistent fused Picard pass, work-stealing split-K ------
__global__ void __launch_bounds__(128, 4)
k_iter(const int* __restrict__ fw, float* __restrict__ out,
       int it, int src, int writeB, int useB) {
    __shared__ __align__(16) unsigned char sBuf[STAGES * STGB];  // pipeline / sZ overlay
    __shared__ float sWp[MR * MR];
    __shared__ int   sTile;
    __shared__ int   sLast;

    const int t = threadIdx.x;
    const int w = t >> 5, lane = t & 31;

    const int fwv = *fw;
    if (it > fwv) return;

    for (int i = t; i < MR * MR; i += 128) sWp[i] = g_Wp[i];

    const __half* Ysrc = g_Yp[src];
    const uint32_t base = (uint32_t)__cvta_generic_to_shared(sBuf);

    // cp.async granule mapping (3 x 16B per thread per chunk)
    const int gA_c = (t >> 1) & 63, gA_s = t & 1;
    const int gY_h = (t >> 6) & 1,  gY_m = (t >> 1) & 31, gY_s = t & 1;
    const uint32_t dA0 = ((0 * 64 + gA_c) * 24 + gA_s * 8) * 2;
    const uint32_t dA1 = ((1 * 64 + gA_c) * 24 + gA_s * 8) * 2;
    const uint32_t dY  = ((gY_h * 32 + gY_m) * 24 + gY_s * 8) * 2;
    const int sA0 = 0 * 1024 + gA_c * 16 + gA_s * 8;
    const int sA1 = 1 * 1024 + gA_c * 16 + gA_s * 8;
    const int sY  = gY_h * 512 + gY_m * 16 + gY_s * 8;

    // ldmatrix per-lane byte offsets
    const int tl = lane >> 3, rl = lane & 7;
    const int aRow = w * 16 + ((tl & 1) << 3) + rl;
    const int aKo  = (tl >> 1) << 3;
    const uint32_t offAhi = (uint32_t)((aRow)      * 24 + aKo) * 2;
    const uint32_t offAlo = (uint32_t)((64 + aRow) * 24 + aKo) * 2;
    const int yM  = ((tl >> 1) << 3) + rl;
    const int yKo = (tl & 1) << 3;
    const uint32_t offYh0 = (uint32_t)((yM)           * 24 + yKo) * 2;
    const uint32_t offYh1 = (uint32_t)((yM + 16)      * 24 + yKo) * 2;
    const uint32_t offYl0 = (uint32_t)((32 + yM)      * 24 + yKo) * 2;
    const uint32_t offYl1 = (uint32_t)((32 + yM + 16) * 24 + yKo) * 2;

    int* tix = &g_tix[it & 31];

    for (;;) {
        // --- steal a tile ---
        __syncthreads();
        if (t == 0) sTile = atomicAdd(tix, 1);
        __syncthreads();
        const int tile = sTile;
        if (tile >= NTILES) return;
        const int nb = tile % NB;
        const int sp = tile / NB;
        const int kbeg = (sp * KCH) / KSPLIT;
        const int kend = ((sp + 1) * KCH) / KSPLIT;
        const __half* Asrc = &g_Apk[(size_t)nb * KCH * 2048];

        auto issue = [&](int kc2) {
            int buf = (kc2 - kbeg) % STAGES;
            const __half* ac = Asrc + (size_t)kc2 * 2048;
            const __half* yc = Ysrc + (size_t)kc2 * 1024;
            uint32_t ab = base + buf * STGB;
            uint32_t yb = ab + 6144;
            cpa16(ab + dA0, ac + sA0);
            cpa16(ab + dA1, ac + sA1);
            cpa16(yb + dY,  yc + sY);
        };

        // prologue: STAGES-1 groups
        #pragma unroll
        for (int p = 0; p < STAGES - 1; p++) {
            issue(kbeg + p);
            asm volatile("cp.async.commit_group;");
        }

        float Cm[4][4], Cs[4][4];
        #pragma unroll
        for (int j = 0; j < 4; j++)
            #pragma unroll
            for (int q = 0; q < 4; q++) { Cm[j][q] = 0.f; Cs[j][q] = 0.f; }

        for (int kc = kbeg; kc < kend; kc++) {
            asm volatile("cp.async.wait_group %0;" :: "n"(STAGES - 2));
            __syncthreads();
            int nkc = kc + STAGES - 1;
            if (nkc < kend) issue(nkc);
            asm volatile("cp.async.commit_group;");

            int buf = (kc - kbeg) % STAGES;
            uint32_t ab = base + buf * STGB;
            uint32_t yb = ab + 6144;

            uint32_t Ah[4], Al[4], Bh0[4], Bh1[4], Bl0[4], Bl1[4];
            ldm4(Ah,  ab + offAhi);
            ldm4(Al,  ab + offAlo);
            ldm4(Bh0, yb + offYh0);
            ldm4(Bh1, yb + offYh1);
            ldm4(Bl0, yb + offYl0);
            ldm4(Bl1, yb + offYl1);

            mma_(Cm[0], Ah, Bh0[0], Bh0[1]);
            mma_(Cm[1], Ah, Bh0[2], Bh0[3]);
            mma_(Cm[2], Ah, Bh1[0], Bh1[1]);
            mma_(Cm[3], Ah, Bh1[2], Bh1[3]);

            mma_(Cs[0], Ah, Bl0[0], Bl0[1]);
            mma_(Cs[1], Ah, Bl0[2], Bl0[3]);
            mma_(Cs[2], Ah, Bl1[0], Bl1[1]);
            mma_(Cs[3], Ah, Bl1[2], Bl1[3]);

            mma_(Cs[0], Al, Bh0[0], Bh0[1]);
            mma_(Cs[1], Al, Bh0[2], Bh0[3]);
            mma_(Cs[2], Al, Bh1[0], Bh1[1]);
            mma_(Cs[3], Al, Bh1[2], Bh1[3]);
        }
        asm volatile("cp.async.wait_group 0;");
        __syncthreads();

        // scatter C frags -> sZ[c][m]  (overlay on pipeline smem)
        float (*sZ)[33] = (float (*)[33])sBuf;
        {
            const int g = lane >> 2, i2 = (lane & 3) << 1;
            const int c = w * 16 + g;
            #pragma unroll
            for (int j = 0; j < 4; j++) {
                int m = j * 8 + i2;
                sZ[c][m]         = Cm[j][0] + Cs[j][0] * INV2048;
                sZ[c][m + 1]     = Cm[j][1] + Cs[j][1] * INV2048;
                sZ[c + 8][m]     = Cm[j][2] + Cs[j][2] * INV2048;
                sZ[c + 8][m + 1] = Cm[j][3] + Cs[j][3] * INV2048;
            }
        }
        __syncthreads();

        // store partial Z (coalesced float4)
        {
            float* gp = &g_Zp[((size_t)(sp * NB + nb)) * 2048];
            #pragma unroll
            for (int q = 0; q < 4; q++) {
                int idx = t * 16 + q * 4;
                int c = idx >> 5, m = idx & 31;
                float4 v = make_float4(sZ[c][m], sZ[c][m + 1], sZ[c][m + 2], sZ[c][m + 3]);
                *reinterpret_cast<float4*>(gp + idx) = v;
            }
        }
        __threadfence();
        __syncthreads();
        if (t == 0) {
            int old = atomicAdd(&g_cnt[nb], 1);
            sLast = (old == KSPLIT - 1);
        }
        __syncthreads();
        if (!sLast) continue;

        // ---- ticket CTA: reduce partials + epilogue ----
        const int col = t >> 1, r0 = (t & 1) << 4;
        const int gcol = nb * BN + col;
        float z[16];
        #pragma unroll
        for (int q = 0; q < 4; q++) {
            float4 acc = make_float4(0.f, 0.f, 0.f, 0.f);
            #pragma unroll
            for (int s2 = 0; s2 < KSPLIT; s2++) {
                const float4* p = reinterpret_cast<const float4*>(
                    &g_Zp[((size_t)(s2 * NB + nb)) * 2048 + col * 32 + r0 + q * 4]);
                float4 v = __ldcg(p);
                acc.x += v.x; acc.y += v.y; acc.z += v.z; acc.w += v.w;
            }
            z[q * 4 + 0] = acc.x; z[q * 4 + 1] = acc.y;
            z[q * 4 + 2] = acc.z; z[q * 4 + 3] = acc.w;
        }

        float* Bp = &g_B[(nb * BN + col) * MR];
        const bool writeOut = (it == fwv);
        const bool writeY   = (it < fwv);

        #pragma unroll
        for (int r = 0; r < 16; r++) {
            int rr = r0 + r;
            float zz = z[r];
            if (useB)   zz += Bp[rr];
            if (writeB) Bp[rr] = zz;
            float xv = fmaxf(zz, 0.0f);
            if (writeOut && gcol < NCOLS) out[(size_t)rr * NCOLS + gcol] = xv;
            sZ[col][rr] = xv;
        }
        __syncthreads();

        if (writeY) {
            int kc = gcol >> 4, kk = gcol & 15;
            __half* Yd = g_Yp[src ^ 1] + (size_t)kc * 1024;
            #pragma unroll
            for (int r = 0; r < 16; r++) {
                int rr = r0 + r;
                float y = 0.f;
                #pragma unroll
                for (int j = 0; j < MR; j++) y += sWp[rr * MR + j] * sZ[col][j];
                __half h, l; hilo(y, h, l);
                Yd[rr * 16 + kk] = h;
                Yd[512 + rr * 16 + kk] = l;
            }
        }
        if (t == 0) g_cnt[nb] = 0;   // reset for next pass / replay
    }
}

// ---------------- launch ----------------
// Inputs: W, Omega_1, Omega_2, X_0, A, U, fw_mitr
extern "C" void kernel_launch(void* const* d_in, const int* in_sizes, int n_in,
                              void* d_out, int out_size) {
    const float* W   = (const float*)d_in[0];
    const float* Om1 = (const float*)d_in[1];
    const float* A   = (const float*)d_in[4];
    const float* U   = (const float*)d_in[5];
    const int*   fw  = (const int*)  d_in[6];
    float*       out = (float*)d_out;

    k_reset<<<1, 128>>>();
    k_project<<<1, 32>>>(W);
    k_convA<<<NB * KCH, 128>>>(A);
    k_T<<<KCH, 128>>>(Om1, U);

    // it = 1: Z = T@A = b ; B := Z ; X1 = relu(b) ; Y1 = Wp@X1
    k_iter<<<GRID, 128>>>(fw, out, 1, 0, 1, 0);
    // it = 2..30
    for (int it = 2; it <= 30; it++)
        k_iter<<<GRID, 128>>>(fw, out, it, (it - 1) & 1, 0, 1);
}

// round 7
// speedup vs baseline: 1.1004x; 1.1004x over previous
#include <cuda_runtime.h>
#include <cuda_fp16.h>
#include <cstdint>

#define MR     32
#define NCOLS  10000
#define KDIM   10000
#define NB     157        // column blocks of 64 (157*64 = 10048 padded)
#define BN     64
#define KCH    625        // k-chunks of 16
#define NPCH   628        // padded chunk count for Y buffers
#define STAGES 5
#define KSPLIT 16
#define STGB   9216       // bytes per pipeline stage (A 6144 + Y 3072)
#define INV2048 (1.0f/2048.0f)

// ---------------- device scratch (allocation-free) ----------------
__device__ __align__(16) __half g_Apk[(size_t)NB * KCH * 2048];     // ~402 MB
__device__ __align__(16) __half g_Yp[2][(size_t)NPCH * 1024];
__device__ __align__(16) float  g_Zp[(size_t)KSPLIT * NB * 2048];   // split-K partials
__device__ float  g_B[NB * BN * MR];
__device__ float  g_Wp[MR * MR];
__device__ int    g_cnt[NB];                                        // zero-init; self-resetting

// ---------------- helpers ----------------
__device__ __forceinline__ void cpa16(uint32_t d, const void* s) {
    asm volatile("cp.async.cg.shared.global [%0], [%1], 16;" :: "r"(d), "l"(s));
}
__device__ __forceinline__ void ldm4(uint32_t* r, uint32_t a) {
    asm volatile("ldmatrix.sync.aligned.m8n8.x4.shared.b16 {%0,%1,%2,%3}, [%4];"
        : "=r"(r[0]), "=r"(r[1]), "=r"(r[2]), "=r"(r[3]) : "r"(a));
}
__device__ __forceinline__ void mma_(float* c, const uint32_t* a, uint32_t b0, uint32_t b1) {
    asm volatile("mma.sync.aligned.m16n8k16.row.col.f32.f16.f16.f32 "
        "{%0,%1,%2,%3}, {%4,%5,%6,%7}, {%8,%9}, {%0,%1,%2,%3};"
        : "+f"(c[0]), "+f"(c[1]), "+f"(c[2]), "+f"(c[3])
        : "r"(a[0]), "r"(a[1]), "r"(a[2]), "r"(a[3]), "r"(b0), "r"(b1));
}
__device__ __forceinline__ void hilo(float v, __half& h, __half& l) {
    h = __float2half_rn(v);
    l = __float2half_rn((v - __half2float(h)) * 2048.0f);
}

// ---------------- 1. W projection (verified) ----------------
__global__ void k_project(const float* __restrict__ W) {
    int r = threadIdx.x;
    if (r >= MR) return;
    float a[32], u[32];
    float s = 0.0f;
    for (int i = 0; i < 32; i++) { a[i] = W[r * 32 + i]; u[i] = fabsf(a[i]); s += u[i]; }
    const float v = 0.99f;
    if (s > v) {
        for (int i = 1; i < 32; i++) {
            float key = u[i]; int j = i - 1;
            while (j >= 0 && u[j] < key) { u[j + 1] = u[j]; j--; }
            u[j + 1] = key;
        }
        float cs = 0.0f; int rho = 0;
        for (int i = 0; i < 32; i++) {
            cs += u[i];
            if (u[i] - (cs - v) / (float)(i + 1) > 0.0f) rho++;
        }
        float cs2 = 0.0f;
        for (int i = 0; i < rho; i++) cs2 += u[i];
        float theta = (cs2 - v) / (float)rho;
        for (int i = 0; i < 32; i++) {
            float m = fmaxf(fabsf(a[i]) - theta, 0.0f);
            a[i] = (a[i] > 0.0f) ? m : ((a[i] < 0.0f) ? -m : 0.0f);
        }
    }
    for (int i = 0; i < 32; i++) g_Wp[r * 32 + i] = a[i];
}

// ---------------- 2. Convert A -> blocked fp16 hi/lo (verified) ----------------
__global__ void k_convA(const float* __restrict__ A) {
    __shared__ __align__(16) float sA[16][68];
    int b  = blockIdx.x;               // nb*KCH + kc
    int nb = b / KCH, kc = b % KCH;
    int t  = threadIdx.x;
    int k0 = kc * 16, c0 = nb * BN;
    for (int e = t; e < 1024; e += 128) {
        int kk = e >> 6, c = e & 63;
        int gc = c0 + c;
        float v0 = 0.0f;
        if (gc < NCOLS) v0 = A[(size_t)(k0 + kk) * NCOLS + gc];
        sA[kk][c] = v0;
    }
    __syncthreads();
    __half* dst = &g_Apk[(size_t)b * 2048];
    for (int e = t; e < 1024; e += 128) {
        int c = e >> 4, kk = e & 15;
        __half h, l; hilo(sA[kk][c], h, l);
        dst[e] = h;
        dst[1024 + e] = l;
    }
}

// ---------------- 3. T = Omega_1 @ U -> Y[0] (verified) ----------------
__global__ void k_T(const float* __restrict__ Om1, const float* __restrict__ U) {
    __shared__ float sOm[MR * 64];
    int t = threadIdx.x;
    for (int i = t; i < MR * 64; i += 128) sOm[i] = Om1[i];
    __syncthreads();
    int kc = blockIdx.x;
    __half* dst = &g_Yp[0][(size_t)kc * 1024];
    for (int e = t; e < 512; e += 128) {
        int m = e >> 4, kk = e & 15;
        int k = kc * 16 + kk;
        float v = 0.f;
        #pragma unroll
        for (int p = 0; p < 64; p++) v += sOm[m * 64 + p] * U[(size_t)p * NCOLS + k];
        __half h, l; hilo(v, h, l);
        dst[m * 16 + kk] = h;
        dst[512 + m * 16 + kk] = l;
    }
}

// ---------------- 4. Fused Picard pass, split-K x16, atomic-ticket epilogue ---
__global__ void __launch_bounds__(128, 4)
k_iter(const int* __restrict__ fw, float* __restrict__ out,
       int it, int src, int writeB, int useB) {
    __shared__ __align__(16) unsigned char sBuf[STAGES * STGB];  // pipeline / sZ overlay
    __shared__ float sWp[MR * MR];
    __shared__ int   sLast;

    const int t = threadIdx.x;
    const int nb = blockIdx.x % NB;
    const int sp = blockIdx.x / NB;
    const int w = t >> 5, lane = t & 31;

    const int fwv = *fw;
    if (it > fwv) return;

    for (int i = t; i < MR * MR; i += 128) sWp[i] = g_Wp[i];

    const int kbeg = (sp * KCH) / KSPLIT;
    const int kend = ((sp + 1) * KCH) / KSPLIT;

    const __half* Asrc = &g_Apk[(size_t)nb * KCH * 2048];
    const __half* Ysrc = g_Yp[src];
    const uint32_t base = (uint32_t)__cvta_generic_to_shared(sBuf);

    // cp.async granule mapping (3 x 16B per thread per chunk)
    const int gA_c = (t >> 1) & 63, gA_s = t & 1;
    const int gY_h = (t >> 6) & 1,  gY_m = (t >> 1) & 31, gY_s = t & 1;
    const uint32_t dA0 = ((0 * 64 + gA_c) * 24 + gA_s * 8) * 2;
    const uint32_t dA1 = ((1 * 64 + gA_c) * 24 + gA_s * 8) * 2;
    const uint32_t dY  = ((gY_h * 32 + gY_m) * 24 + gY_s * 8) * 2;
    const int sA0 = 0 * 1024 + gA_c * 16 + gA_s * 8;
    const int sA1 = 1 * 1024 + gA_c * 16 + gA_s * 8;
    const int sY  = gY_h * 512 + gY_m * 16 + gY_s * 8;

    // ldmatrix per-lane byte offsets
    const int tl = lane >> 3, rl = lane & 7;
    const int aRow = w * 16 + ((tl & 1) << 3) + rl;
    const int aKo  = (tl >> 1) << 3;
    const uint32_t offAhi = (uint32_t)((aRow)      * 24 + aKo) * 2;
    const uint32_t offAlo = (uint32_t)((64 + aRow) * 24 + aKo) * 2;
    const int yM  = ((tl >> 1) << 3) + rl;
    const int yKo = (tl & 1) << 3;
    const uint32_t offYh0 = (uint32_t)((yM)           * 24 + yKo) * 2;
    const uint32_t offYh1 = (uint32_t)((yM + 16)      * 24 + yKo) * 2;
    const uint32_t offYl0 = (uint32_t)((32 + yM)      * 24 + yKo) * 2;
    const uint32_t offYl1 = (uint32_t)((32 + yM + 16) * 24 + yKo) * 2;

    auto issue = [&](int kc2) {
        int buf = (kc2 - kbeg) % STAGES;
        const __half* ac = Asrc + (size_t)kc2 * 2048;
        const __half* yc = Ysrc + (size_t)kc2 * 1024;
        uint32_t ab = base + buf * STGB;
        uint32_t yb = ab + 6144;
        cpa16(ab + dA0, ac + sA0);
        cpa16(ab + dA1, ac + sA1);
        cpa16(yb + dY,  yc + sY);
    };

    // prologue: STAGES-1 groups
    #pragma unroll
    for (int p = 0; p < STAGES - 1; p++) {
        issue(kbeg + p);
        asm volatile("cp.async.commit_group;");
    }

    float Cm[4][4], Cs[4][4];
    #pragma unroll
    for (int j = 0; j < 4; j++)
        #pragma unroll
        for (int q = 0; q < 4; q++) { Cm[j][q] = 0.f; Cs[j][q] = 0.f; }

    for (int kc = kbeg; kc < kend; kc++) {
        asm volatile("cp.async.wait_group %0;" :: "n"(STAGES - 2));
        __syncthreads();
        int nkc = kc + STAGES - 1;
        if (nkc < kend) issue(nkc);
        asm volatile("cp.async.commit_group;");

        int buf = (kc - kbeg) % STAGES;
        uint32_t ab = base + buf * STGB;
        uint32_t yb = ab + 6144;

        uint32_t Ah[4], Al[4], Bh0[4], Bh1[4], Bl0[4], Bl1[4];
        ldm4(Ah,  ab + offAhi);
        ldm4(Al,  ab + offAlo);
        ldm4(Bh0, yb + offYh0);
        ldm4(Bh1, yb + offYh1);
        ldm4(Bl0, yb + offYl0);
        ldm4(Bl1, yb + offYl1);

        mma_(Cm[0], Ah, Bh0[0], Bh0[1]);
        mma_(Cm[1], Ah, Bh0[2], Bh0[3]);
        mma_(Cm[2], Ah, Bh1[0], Bh1[1]);
        mma_(Cm[3], Ah, Bh1[2], Bh1[3]);

        mma_(Cs[0], Ah, Bl0[0], Bl0[1]);
        mma_(Cs[1], Ah, Bl0[2], Bl0[3]);
        mma_(Cs[2], Ah, Bl1[0], Bl1[1]);
        mma_(Cs[3], Ah, Bl1[2], Bl1[3]);

        mma_(Cs[0], Al, Bh0[0], Bh0[1]);
        mma_(Cs[1], Al, Bh0[2], Bh0[3]);
        mma_(Cs[2], Al, Bh1[0], Bh1[1]);
        mma_(Cs[3], Al, Bh1[2], Bh1[3]);
    }
    asm volatile("cp.async.wait_group 0;");
    __syncthreads();

    // scatter C frags -> sZ[c][m]  (overlay on pipeline smem)
    float (*sZ)[33] = (float (*)[33])sBuf;
    {
        const int g = lane >> 2, i2 = (lane & 3) << 1;
        const int c = w * 16 + g;
        #pragma unroll
        for (int j = 0; j < 4; j++) {
            int m = j * 8 + i2;
            sZ[c][m]         = Cm[j][0] + Cs[j][0] * INV2048;
            sZ[c][m + 1]     = Cm[j][1] + Cs[j][1] * INV2048;
            sZ[c + 8][m]     = Cm[j][2] + Cs[j][2] * INV2048;
            sZ[c + 8][m + 1] = Cm[j][3] + Cs[j][3] * INV2048;
        }
    }
    __syncthreads();

    // store partial Z (coalesced float4)
    {
        float* gp = &g_Zp[((size_t)(sp * NB + nb)) * 2048];
        #pragma unroll
        for (int q = 0; q < 4; q++) {
            int idx = t * 16 + q * 4;
            int c = idx >> 5, m = idx & 31;
            float4 v = make_float4(sZ[c][m], sZ[c][m + 1], sZ[c][m + 2], sZ[c][m + 3]);
            *reinterpret_cast<float4*>(gp + idx) = v;
        }
    }
    __threadfence();
    __syncthreads();
    if (t == 0) {
        int old = atomicAdd(&g_cnt[nb], 1);
        sLast = (old == KSPLIT - 1);
    }
    __syncthreads();
    if (!sLast) return;

    // ---- ticket CTA: reduce partials + epilogue ----
    const int col = t >> 1, r0 = (t & 1) << 4;
    const int gcol = nb * BN + col;
    float z[16];
    #pragma unroll
    for (int q = 0; q < 4; q++) {
        float4 acc = make_float4(0.f, 0.f, 0.f, 0.f);
        #pragma unroll
        for (int s2 = 0; s2 < KSPLIT; s2++) {
            const float4* p = reinterpret_cast<const float4*>(
                &g_Zp[((size_t)(s2 * NB + nb)) * 2048 + col * 32 + r0 + q * 4]);
            float4 v = __ldcg(p);
            acc.x += v.x; acc.y += v.y; acc.z += v.z; acc.w += v.w;
        }
        z[q * 4 + 0] = acc.x; z[q * 4 + 1] = acc.y;
        z[q * 4 + 2] = acc.z; z[q * 4 + 3] = acc.w;
    }

    float* Bp = &g_B[(nb * BN + col) * MR];
    const bool writeOut = (it == fwv);
    const bool writeY   = (it < fwv);

    #pragma unroll
    for (int r = 0; r < 16; r++) {
        int rr = r0 + r;
        float zz = z[r];
        if (useB)   zz += Bp[rr];
        if (writeB) Bp[rr] = zz;
        float xv = fmaxf(zz, 0.0f);
        if (writeOut && gcol < NCOLS) out[(size_t)rr * NCOLS + gcol] = xv;
        sZ[col][rr] = xv;
    }
    __syncthreads();

    if (writeY) {
        int kc = gcol >> 4, kk = gcol & 15;
        __half* Yd = g_Yp[src ^ 1] + (size_t)kc * 1024;
        #pragma unroll
        for (int r = 0; r < 16; r++) {
            int rr = r0 + r;
            float y = 0.f;
            #pragma unroll
            for (int j = 0; j < MR; j++) y += sWp[rr * MR + j] * sZ[col][j];
            __half h, l; hilo(y, h, l);
            Yd[rr * 16 + kk] = h;
            Yd[512 + rr * 16 + kk] = l;
        }
    }
    if (t == 0) g_cnt[nb] = 0;   // reset for next pass / replay
}

// ---------------- launch ----------------
// Inputs: W, Omega_1, Omega_2, X_0, A, U, fw_mitr
extern "C" void kernel_launch(void* const* d_in, const int* in_sizes, int n_in,
                              void* d_out, int out_size) {
    const float* W   = (const float*)d_in[0];
    const float* Om1 = (const float*)d_in[1];
    const float* A   = (const float*)d_in[4];
    const float* U   = (const float*)d_in[5];
    const int*   fw  = (const int*)  d_in[6];
    float*       out = (float*)d_out;

    k_project<<<1, 32>>>(W);
    k_convA<<<NB * KCH, 128>>>(A);
    k_T<<<KCH, 128>>>(Om1, U);

    // it = 1: Z = T@A = b ; B := Z ; X1 = relu(b) ; Y1 = Wp@X1
    k_iter<<<NB * KSPLIT, 128>>>(fw, out, 1, 0, 1, 0);
    // it = 2..30
    for (int it = 2; it <= 30; it++)
        k_iter<<<NB * KSPLIT, 128>>>(fw, out, it, (it - 1) & 1, 0, 1);
}

// round 9
// speedup vs baseline: 1.1017x; 1.0012x over previous
#include <cuda_runtime.h>
#include <cuda_fp16.h>
#include <cstdint>

#define MR     32
#define NCOLS  10000
#define KDIM   10000
#define NB     157        // column blocks of 64 (157*64 = 10048 padded)
#define BN     64
#define KCH    625        // k-chunks of 16
#define NPCH   628        // padded chunk count for Y buffers
#define STAGES 6
#define KSPLIT 16
#define STGB   9216       // bytes per pipeline stage (A 6144 + Y 3072)
#define INV2048 (1.0f/2048.0f)

// ---------------- device scratch (allocation-free) ----------------
__device__ __align__(16) __half g_Apk[(size_t)NB * KCH * 2048];     // ~402 MB
__device__ __align__(16) __half g_Yp[2][(size_t)NPCH * 1024];
__device__ __align__(16) float  g_Zp[(size_t)KSPLIT * NB * 2048];   // split-K partials
__device__ float  g_B[NB * BN * MR];
__device__ float  g_Wp[MR * MR];
__device__ int    g_cnt[NB];                                        // zero-init; self-resetting

// ---------------- helpers ----------------
__device__ __forceinline__ void cpa16(uint32_t d, const void* s) {
    asm volatile("cp.async.cg.shared.global [%0], [%1], 16;" :: "r"(d), "l"(s));
}
__device__ __forceinline__ void ldm4(uint32_t* r, uint32_t a) {
    asm volatile("ldmatrix.sync.aligned.m8n8.x4.shared.b16 {%0,%1,%2,%3}, [%4];"
        : "=r"(r[0]), "=r"(r[1]), "=r"(r[2]), "=r"(r[3]) : "r"(a));
}
__device__ __forceinline__ void mma_(float* c, const uint32_t* a, uint32_t b0, uint32_t b1) {
    asm volatile("mma.sync.aligned.m16n8k16.row.col.f32.f16.f16.f32 "
        "{%0,%1,%2,%3}, {%4,%5,%6,%7}, {%8,%9}, {%0,%1,%2,%3};"
        : "+f"(c[0]), "+f"(c[1]), "+f"(c[2]), "+f"(c[3])
        : "r"(a[0]), "r"(a[1]), "r"(a[2]), "r"(a[3]), "r"(b0), "r"(b1));
}
__device__ __forceinline__ void hilo(float v, __half& h, __half& l) {
    h = __float2half_rn(v);
    l = __float2half_rn((v - __half2float(h)) * 2048.0f);
}

// ---------------- 1. W projection (verified) ----------------
__global__ void k_project(const float* __restrict__ W) {
    int r = threadIdx.x;
    if (r >= MR) return;
    float a[32], u[32];
    float s = 0.0f;
    for (int i = 0; i < 32; i++) { a[i] = W[r * 32 + i]; u[i] = fabsf(a[i]); s += u[i]; }
    const float v = 0.99f;
    if (s > v) {
        for (int i = 1; i < 32; i++) {
            float key = u[i]; int j = i - 1;
            while (j >= 0 && u[j] < key) { u[j + 1] = u[j]; j--; }
            u[j + 1] = key;
        }
        float cs = 0.0f; int rho = 0;
        for (int i = 0; i < 32; i++) {
            cs += u[i];
            if (u[i] - (cs - v) / (float)(i + 1) > 0.0f) rho++;
        }
        float cs2 = 0.0f;
        for (int i = 0; i < rho; i++) cs2 += u[i];
        float theta = (cs2 - v) / (float)rho;
        for (int i = 0; i < 32; i++) {
            float m = fmaxf(fabsf(a[i]) - theta, 0.0f);
            a[i] = (a[i] > 0.0f) ? m : ((a[i] < 0.0f) ? -m : 0.0f);
        }
    }
    for (int i = 0; i < 32; i++) g_Wp[r * 32 + i] = a[i];
}

// ---------------- 2. Convert A -> blocked fp16 hi/lo (verified) ----------------
__global__ void k_convA(const float* __restrict__ A) {
    __shared__ __align__(16) float sA[16][68];
    int b  = blockIdx.x;               // nb*KCH + kc
    int nb = b / KCH, kc = b % KCH;
    int t  = threadIdx.x;
    int k0 = kc * 16, c0 = nb * BN;
    for (int e = t; e < 1024; e += 128) {
        int kk = e >> 6, c = e & 63;
        int gc = c0 + c;
        float v0 = 0.0f;
        if (gc < NCOLS) v0 = A[(size_t)(k0 + kk) * NCOLS + gc];
        sA[kk][c] = v0;
    }
    __syncthreads();
    __half* dst = &g_Apk[(size_t)b * 2048];
    for (int e = t; e < 1024; e += 128) {
        int c = e >> 4, kk = e & 15;
        __half h, l; hilo(sA[kk][c], h, l);
        dst[e] = h;
        dst[1024 + e] = l;
    }
}

// ---------------- 3. T = Omega_1 @ U -> Y[0] (verified) ----------------
__global__ void k_T(const float* __restrict__ Om1, const float* __restrict__ U) {
    __shared__ float sOm[MR * 64];
    int t = threadIdx.x;
    for (int i = t; i < MR * 64; i += 128) sOm[i] = Om1[i];
    __syncthreads();
    int kc = blockIdx.x;
    __half* dst = &g_Yp[0][(size_t)kc * 1024];
    for (int e = t; e < 512; e += 128) {
        int m = e >> 4, kk = e & 15;
        int k = kc * 16 + kk;
        float v = 0.f;
        #pragma unroll
        for (int p = 0; p < 64; p++) v += sOm[m * 64 + p] * U[(size_t)p * NCOLS + k];
        __half h, l; hilo(v, h, l);
        dst[m * 16 + kk] = h;
        dst[512 + m * 16 + kk] = l;
    }
}

// ---------------- 4. Fused Picard pass, chunk-PAIR pipeline ----------------
__global__ void __launch_bounds__(128, 4)
k_iter(const int* __restrict__ fw, float* __restrict__ out,
       int it, int src, int writeB, int useB) {
    __shared__ __align__(16) unsigned char sBuf[STAGES * STGB];  // pipeline / overlay
    __shared__ int sLast;

    const int t = threadIdx.x;
    const int nb = blockIdx.x % NB;
    const int sp = blockIdx.x / NB;
    const int w = t >> 5, lane = t & 31;

    const int fwv = *fw;
    if (it > fwv) return;

    const int kbeg = (sp * KCH) / KSPLIT;
    const int kend = ((sp + 1) * KCH) / KSPLIT;

    const __half* Asrc = &g_Apk[(size_t)nb * KCH * 2048];
    const __half* Ysrc = g_Yp[src];
    const uint32_t base = (uint32_t)__cvta_generic_to_shared(sBuf);

    // cp.async granule mapping (3 x 16B per thread per chunk)
    const int gA_c = (t >> 1) & 63, gA_s = t & 1;
    const int gY_h = (t >> 6) & 1,  gY_m = (t >> 1) & 31, gY_s = t & 1;
    const uint32_t dA0 = ((0 * 64 + gA_c) * 24 + gA_s * 8) * 2;
    const uint32_t dA1 = ((1 * 64 + gA_c) * 24 + gA_s * 8) * 2;
    const uint32_t dY  = ((gY_h * 32 + gY_m) * 24 + gY_s * 8) * 2;
    const int sA0 = 0 * 1024 + gA_c * 16 + gA_s * 8;
    const int sA1 = 1 * 1024 + gA_c * 16 + gA_s * 8;
    const int sY  = gY_h * 512 + gY_m * 16 + gY_s * 8;

    // ldmatrix per-lane byte offsets
    const int tl = lane >> 3, rl = lane & 7;
    const int aRow = w * 16 + ((tl & 1) << 3) + rl;
    const int aKo  = (tl >> 1) << 3;
    const uint32_t offAhi = (uint32_t)((aRow)      * 24 + aKo) * 2;
    const uint32_t offAlo = (uint32_t)((64 + aRow) * 24 + aKo) * 2;
    const int yM  = ((tl >> 1) << 3) + rl;
    const int yKo = (tl & 1) << 3;
    const uint32_t offYh0 = (uint32_t)((yM)           * 24 + yKo) * 2;
    const uint32_t offYh1 = (uint32_t)((yM + 16)      * 24 + yKo) * 2;
    const uint32_t offYl0 = (uint32_t)((32 + yM)      * 24 + yKo) * 2;
    const uint32_t offYl1 = (uint32_t)((32 + yM + 16) * 24 + yKo) * 2;

    auto issue1 = [&](int kc2) {
        int buf = (kc2 - kbeg) % STAGES;
        const __half* ac = Asrc + (size_t)kc2 * 2048;
        const __half* yc = Ysrc + (size_t)kc2 * 1024;
        uint32_t ab = base + buf * STGB;
        uint32_t yb = ab + 6144;
        cpa16(ab + dA0, ac + sA0);
        cpa16(ab + dA1, ac + sA1);
        cpa16(yb + dY,  yc + sY);
    };
    // issue a pair group (chunks c, c+1, guarded) + single commit
    auto issueg = [&](int c) {
        if (c < kend) {
            issue1(c);
            if (c + 1 < kend) issue1(c + 1);
        }
        asm volatile("cp.async.commit_group;");
    };

    float Cm[4][4], Cs[4][4];
    #pragma unroll
    for (int j = 0; j < 4; j++)
        #pragma unroll
        for (int q = 0; q < 4; q++) { Cm[j][q] = 0.f; Cs[j][q] = 0.f; }

    auto compute = [&](int kc) {
        int buf = (kc - kbeg) % STAGES;
        uint32_t ab = base + buf * STGB;
        uint32_t yb = ab + 6144;

        uint32_t Ah[4], Al[4], Bh0[4], Bh1[4], Bl0[4], Bl1[4];
        ldm4(Ah,  ab + offAhi);
        ldm4(Al,  ab + offAlo);
        ldm4(Bh0, yb + offYh0);
        ldm4(Bh1, yb + offYh1);
        ldm4(Bl0, yb + offYl0);
        ldm4(Bl1, yb + offYl1);

        mma_(Cm[0], Ah, Bh0[0], Bh0[1]);
        mma_(Cm[1], Ah, Bh0[2], Bh0[3]);
        mma_(Cm[2], Ah, Bh1[0], Bh1[1]);
        mma_(Cm[3], Ah, Bh1[2], Bh1[3]);

        mma_(Cs[0], Ah, Bl0[0], Bl0[1]);
        mma_(Cs[1], Ah, Bl0[2], Bl0[3]);
        mma_(Cs[2], Ah, Bl1[0], Bl1[1]);
        mma_(Cs[3], Ah, Bl1[2], Bl1[3]);

        mma_(Cs[0], Al, Bh0[0], Bh0[1]);
        mma_(Cs[1], Al, Bh0[2], Bh0[3]);
        mma_(Cs[2], Al, Bh1[0], Bh1[1]);
        mma_(Cs[3], Al, Bh1[2], Bh1[3]);
    };

    // prologue: 2 pair-groups
    issueg(kbeg);
    issueg(kbeg + 2);

    for (int c = kbeg; c < kend; c += 2) {
        asm volatile("cp.async.wait_group 1;");
        __syncthreads();
        issueg(c + 4);
        compute(c);
        if (c + 1 < kend) compute(c + 1);
    }
    asm volatile("cp.async.wait_group 0;");
    __syncthreads();

    // scatter C frags -> sZ[c][m]  (overlay on pipeline smem)
    float (*sZ)[33] = (float (*)[33])sBuf;
    {
        const int g = lane >> 2, i2 = (lane & 3) << 1;
        const int c = w * 16 + g;
        #pragma unroll
        for (int j = 0; j < 4; j++) {
            int m = j * 8 + i2;
            sZ[c][m]         = Cm[j][0] + Cs[j][0] * INV2048;
            sZ[c][m + 1]     = Cm[j][1] + Cs[j][1] * INV2048;
            sZ[c + 8][m]     = Cm[j][2] + Cs[j][2] * INV2048;
            sZ[c + 8][m + 1] = Cm[j][3] + Cs[j][3] * INV2048;
        }
    }
    __syncthreads();

    // store partial Z (coalesced float4)
    {
        float* gp = &g_Zp[((size_t)(sp * NB + nb)) * 2048];
        #pragma unroll
        for (int q = 0; q < 4; q++) {
            int idx = t * 16 + q * 4;
            int c = idx >> 5, m = idx & 31;
            float4 v = make_float4(sZ[c][m], sZ[c][m + 1], sZ[c][m + 2], sZ[c][m + 3]);
            *reinterpret_cast<float4*>(gp + idx) = v;
        }
    }
    __threadfence();
    __syncthreads();
    if (t == 0) {
        int old = atomicAdd(&g_cnt[nb], 1);
        sLast = (old == KSPLIT - 1);
    }
    __syncthreads();
    if (!sLast) return;

    // ---- ticket CTA: reduce partials + epilogue ----
    float* sWp = (float*)(sBuf + 64 * 33 * 4);     // overlay after sZ
    for (int i = t; i < MR * MR; i += 128) sWp[i] = g_Wp[i];

    const int col = t >> 1, r0 = (t & 1) << 4;
    const int gcol = nb * BN + col;
    float z[16];
    #pragma unroll
    for (int q = 0; q < 4; q++) {
        float4 acc = make_float4(0.f, 0.f, 0.f, 0.f);
        #pragma unroll
        for (int s2 = 0; s2 < KSPLIT; s2++) {
            const float4* p = reinterpret_cast<const float4*>(
                &g_Zp[((size_t)(s2 * NB + nb)) * 2048 + col * 32 + r0 + q * 4]);
            float4 v = __ldcg(p);
            acc.x += v.x; acc.y += v.y; acc.z += v.z; acc.w += v.w;
        }
        z[q * 4 + 0] = acc.x; z[q * 4 + 1] = acc.y;
        z[q * 4 + 2] = acc.z; z[q * 4 + 3] = acc.w;
    }

    float* Bp = &g_B[(nb * BN + col) * MR];
    const bool writeOut = (it == fwv);
    const bool writeY   = (it < fwv);

    #pragma unroll
    for (int r = 0; r < 16; r++) {
        int rr = r0 + r;
        float zz = z[r];
        if (useB)   zz += Bp[rr];
        if (writeB) Bp[rr] = zz;
        float xv = fmaxf(zz, 0.0f);
        if (writeOut && gcol < NCOLS) out[(size_t)rr * NCOLS + gcol] = xv;
        sZ[col][rr] = xv;
    }
    __syncthreads();

    if (writeY) {
        int kc = gcol >> 4, kk = gcol & 15;
        __half* Yd = g_Yp[src ^ 1] + (size_t)kc * 1024;
        #pragma unroll
        for (int r = 0; r < 16; r++) {
            int rr = r0 + r;
            float y = 0.f;
            #pragma unroll
            for (int j = 0; j < MR; j++) y += sWp[rr * MR + j] * sZ[col][j];
            __half h, l; hilo(y, h, l);
            Yd[rr * 16 + kk] = h;
            Yd[512 + rr * 16 + kk] = l;
        }
    }
    if (t == 0) g_cnt[nb] = 0;   // reset for next pass / replay
}

// ---------------- launch ----------------
// Inputs: W, Omega_1, Omega_2, X_0, A, U, fw_mitr
extern "C" void kernel_launch(void* const* d_in, const int* in_sizes, int n_in,
                              void* d_out, int out_size) {
    const float* W   = (const float*)d_in[0];
    const float* Om1 = (const float*)d_in[1];
    const float* A   = (const float*)d_in[4];
    const float* U   = (const float*)d_in[5];
    const int*   fw  = (const int*)  d_in[6];
    float*       out = (float*)d_out;

    k_project<<<1, 32>>>(W);
    k_convA<<<NB * KCH, 128>>>(A);
    k_T<<<KCH, 128>>>(Om1, U);

    // it = 1: Z = T@A = b ; B := Z ; X1 = relu(b) ; Y1 = Wp@X1
    k_iter<<<NB * KSPLIT, 128>>>(fw, out, 1, 0, 1, 0);
    // it = 2..30
    for (int it = 2; it <= 30; it++)
        k_iter<<<NB * KSPLIT, 128>>>(fw, out, it, (it - 1) & 1, 0, 1);
}